// round 5
// baseline (speedup 1.0000x reference)
#include <cuda_runtime.h>
#include <stdint.h>

#define IN_CH   128
#define OUT_CH  64
#define N_MAX   100000
#define E_MAX   1600000
#define SCAN_B  1024
#define NBLK    ((N_MAX + SCAN_B - 1) / SCAN_B)   // 98

// Scratch (device globals — no runtime allocation allowed)
__device__ float g_h[(size_t)N_MAX * OUT_CH];   // 25.6 MB: h = x @ W
__device__ float g_dinv[N_MAX];
__device__ int   g_deg[N_MAX];                  // includes self loop
__device__ int   g_off[N_MAX];                  // CSR offsets (edges only)
__device__ int   g_cur[N_MAX];                  // fill cursors
__device__ int   g_bsum[NBLK];                  // per-block sums for scan
__device__ int2  g_csr[E_MAX];                  // .x = src, .y = bitcast(norm)

// ---------------------------------------------------------------------------
// Degree pipeline
// ---------------------------------------------------------------------------
__global__ void deg_init_kernel(int n) {
    int i = blockIdx.x * blockDim.x + threadIdx.x;
    if (i < n) g_deg[i] = 1;  // self loop
}

__global__ void deg_count_kernel(const int* __restrict__ dst, int e) {
    int i = blockIdx.x * blockDim.x + threadIdx.x;
    if (i < e) atomicAdd(&g_deg[dst[i]], 1);
}

__global__ void dinv_kernel(int n) {
    int i = blockIdx.x * blockDim.x + threadIdx.x;
    if (i < n) g_dinv[i] = rsqrtf((float)g_deg[i]);
}

// ---------------------------------------------------------------------------
// Hierarchical scan of (deg-1): block-local scan + block sums
// ---------------------------------------------------------------------------
__global__ __launch_bounds__(SCAN_B)
void scan_block_kernel(int n) {
    __shared__ int s[SCAN_B];
    int tid = threadIdx.x;
    int i = blockIdx.x * SCAN_B + tid;
    int c = (i < n) ? (g_deg[i] - 1) : 0;
    s[tid] = c;
    __syncthreads();
#pragma unroll
    for (int off = 1; off < SCAN_B; off <<= 1) {
        int v = (tid >= off) ? s[tid - off] : 0;
        __syncthreads();
        s[tid] += v;
        __syncthreads();
    }
    if (i < n) g_off[i] = s[tid] - c;   // exclusive within block
    if (tid == SCAN_B - 1) g_bsum[blockIdx.x] = s[tid];
}

__global__ __launch_bounds__(128)
void scan_bsums_kernel() {
    __shared__ int s[128];
    int tid = threadIdx.x;
    int v = (tid < NBLK) ? g_bsum[tid] : 0;
    s[tid] = v;
    __syncthreads();
#pragma unroll
    for (int off = 1; off < 128; off <<= 1) {
        int t = (tid >= off) ? s[tid - off] : 0;
        __syncthreads();
        s[tid] += t;
        __syncthreads();
    }
    if (tid < NBLK) g_bsum[tid] = s[tid] - v;  // exclusive
}

__global__ __launch_bounds__(SCAN_B)
void scan_apply_kernel(int n) {
    int i = blockIdx.x * SCAN_B + threadIdx.x;
    if (i < n) {
        int o = g_off[i] + g_bsum[blockIdx.x];
        g_off[i] = o;
        g_cur[i] = o;
    }
}

// ---------------------------------------------------------------------------
// CSR fill: bucket edges by destination, precompute norm per edge
// ---------------------------------------------------------------------------
__global__ __launch_bounds__(256)
void csr_fill_kernel(const int* __restrict__ src, const int* __restrict__ dst,
                     int e) {
    int i = blockIdx.x * blockDim.x + threadIdx.x;
    if (i >= e) return;
    int r = src[i];
    int c = dst[i];
    float norm = g_dinv[r] * g_dinv[c];
    int p = atomicAdd(&g_cur[c], 1);
    g_csr[p] = make_int2(r, __float_as_int(norm));
}

// ---------------------------------------------------------------------------
// GEMM: h = x @ W  (fp32, 128x64 tile per block, 8x4 per thread)
// ---------------------------------------------------------------------------
__global__ __launch_bounds__(256, 3)
void gemm_kernel(const float* __restrict__ x, const float* __restrict__ W,
                 int n) {
    __shared__ float xs[128][33];     // +1 pad vs bank conflicts
    __shared__ float ws[32][OUT_CH];  // k-chunk x all 64 cols

    const int tx  = threadIdx.x;      // 0..15 -> 4 cols each
    const int ty  = threadIdx.y;      // 0..15 -> 8 rows each
    const int tid = ty * 16 + tx;
    const int row0 = blockIdx.x * 128;

    float acc[8][4];
#pragma unroll
    for (int i = 0; i < 8; i++)
#pragma unroll
        for (int j = 0; j < 4; j++) acc[i][j] = 0.0f;

    for (int kc = 0; kc < IN_CH; kc += 32) {
#pragma unroll
        for (int t = 0; t < 4; t++) {
            int li = tid + t * 256;     // 0..1023
            int r  = li >> 3;           // 0..127
            int k4 = li & 7;
            float4 v = make_float4(0.f, 0.f, 0.f, 0.f);
            if (row0 + r < n)
                v = *(const float4*)(x + (size_t)(row0 + r) * IN_CH + kc + k4 * 4);
            xs[r][k4 * 4 + 0] = v.x;
            xs[r][k4 * 4 + 1] = v.y;
            xs[r][k4 * 4 + 2] = v.z;
            xs[r][k4 * 4 + 3] = v.w;
        }
#pragma unroll
        for (int t = 0; t < 2; t++) {
            int li = tid + t * 256;
            int k  = li >> 4;
            int c4 = li & 15;
            *(float4*)&ws[k][c4 * 4] =
                *(const float4*)(W + (size_t)(kc + k) * OUT_CH + c4 * 4);
        }
        __syncthreads();

#pragma unroll
        for (int kk = 0; kk < 32; kk++) {
            float4 b = *(float4*)&ws[kk][tx * 4];
#pragma unroll
            for (int i = 0; i < 8; i++) {
                float a = xs[ty * 8 + i][kk];
                acc[i][0] += a * b.x;
                acc[i][1] += a * b.y;
                acc[i][2] += a * b.z;
                acc[i][3] += a * b.w;
            }
        }
        __syncthreads();
    }

#pragma unroll
    for (int i = 0; i < 8; i++) {
        int r = row0 + ty * 8 + i;
        if (r < n) {
            *(float4*)(g_h + (size_t)r * OUT_CH + tx * 4) =
                make_float4(acc[i][0], acc[i][1], acc[i][2], acc[i][3]);
        }
    }
}

// ---------------------------------------------------------------------------
// Aggregate: 16 threads per node (one float4 column each). Registers
// accumulate in-edges from CSR + self loop; fused bias + ReLU on store.
// ---------------------------------------------------------------------------
__global__ __launch_bounds__(256)
void aggregate_kernel(const float* __restrict__ b, float* __restrict__ out,
                      int n) {
    int idx = blockIdx.x * blockDim.x + threadIdx.x;
    int v = idx >> 4;
    if (v >= n) return;
    int q = idx & 15;

    float dv = g_dinv[v];
    float d2 = dv * dv;

    // self-loop contribution
    float4 acc = *((const float4*)(g_h + (size_t)v * OUT_CH) + q);
    acc.x *= d2; acc.y *= d2; acc.z *= d2; acc.w *= d2;

    int j = g_off[v];
    const int e = j + (g_deg[v] - 1);

    // 4-way unroll for MLP on the random h gathers
    for (; j + 3 < e; j += 4) {
        int2 c0 = g_csr[j + 0];
        int2 c1 = g_csr[j + 1];
        int2 c2 = g_csr[j + 2];
        int2 c3 = g_csr[j + 3];
        float4 h0 = *((const float4*)(g_h + (size_t)c0.x * OUT_CH) + q);
        float4 h1 = *((const float4*)(g_h + (size_t)c1.x * OUT_CH) + q);
        float4 h2 = *((const float4*)(g_h + (size_t)c2.x * OUT_CH) + q);
        float4 h3 = *((const float4*)(g_h + (size_t)c3.x * OUT_CH) + q);
        float n0 = __int_as_float(c0.y), n1 = __int_as_float(c1.y);
        float n2 = __int_as_float(c2.y), n3 = __int_as_float(c3.y);
        acc.x += n0 * h0.x + n1 * h1.x + n2 * h2.x + n3 * h3.x;
        acc.y += n0 * h0.y + n1 * h1.y + n2 * h2.y + n3 * h3.y;
        acc.z += n0 * h0.z + n1 * h1.z + n2 * h2.z + n3 * h3.z;
        acc.w += n0 * h0.w + n1 * h1.w + n2 * h2.w + n3 * h3.w;
    }
    for (; j < e; j++) {
        int2 c = g_csr[j];
        float nm = __int_as_float(c.y);
        float4 hv = *((const float4*)(g_h + (size_t)c.x * OUT_CH) + q);
        acc.x += nm * hv.x; acc.y += nm * hv.y;
        acc.z += nm * hv.z; acc.w += nm * hv.w;
    }

    float4 bb = ((const float4*)b)[q];
    acc.x = fmaxf(acc.x + bb.x, 0.f);
    acc.y = fmaxf(acc.y + bb.y, 0.f);
    acc.z = fmaxf(acc.z + bb.z, 0.f);
    acc.w = fmaxf(acc.w + bb.w, 0.f);
    *((float4*)(out + (size_t)v * OUT_CH) + q) = acc;
}

// ---------------------------------------------------------------------------
extern "C" void kernel_launch(void* const* d_in, const int* in_sizes, int n_in,
                              void* d_out, int out_size) {
    const float* x  = (const float*)d_in[0];
    const int*   ei = (const int*)d_in[1];
    const float* W  = (const float*)d_in[2];
    const float* b  = (const float*)d_in[3];
    float*       out = (float*)d_out;

    const int n = in_sizes[0] / IN_CH;   // 100000
    const int e = in_sizes[1] / 2;       // 1600000
    const int* src = ei;                 // edge_index[0]
    const int* dst = ei + e;             // edge_index[1]

    deg_init_kernel<<<(n + 255) / 256, 256>>>(n);
    deg_count_kernel<<<(e + 255) / 256, 256>>>(dst, e);
    dinv_kernel<<<(n + 255) / 256, 256>>>(n);

    int nblk = (n + SCAN_B - 1) / SCAN_B;
    scan_block_kernel<<<nblk, SCAN_B>>>(n);
    scan_bsums_kernel<<<1, 128>>>();
    scan_apply_kernel<<<nblk, SCAN_B>>>(n);

    csr_fill_kernel<<<(e + 255) / 256, 256>>>(src, dst, e);

    dim3 tb(16, 16);
    gemm_kernel<<<(n + 127) / 128, tb>>>(x, W, n);

    long ag_threads = (long)n * 16;
    aggregate_kernel<<<(int)((ag_threads + 255) / 256), 256>>>(b, out, n);
}

// round 6
// speedup vs baseline: 1.1345x; 1.1345x over previous
#include <cuda_runtime.h>
#include <stdint.h>

#define IN_CH   128
#define OUT_CH  64
#define N_MAX   100000
#define E_MAX   1600000
#define SCAN_B  1024
#define NBLK    ((N_MAX + SCAN_B - 1) / SCAN_B)   // 98

// Scratch (device globals — no runtime allocation allowed)
__device__ float g_h[(size_t)N_MAX * OUT_CH];   // 25.6 MB: h = x @ W (unscaled)
__device__ float g_dinv[N_MAX];
__device__ int   g_deg[N_MAX];                  // includes self loop
__device__ int   g_off[N_MAX];                  // CSR offsets (edges only)
__device__ int   g_cur[N_MAX];                  // fill cursors
__device__ int   g_bsum[NBLK];                  // per-block sums for scan
__device__ int   g_csr[E_MAX];                  // src node per edge (dst-bucketed)

// ---------------------------------------------------------------------------
// Degree pipeline
// ---------------------------------------------------------------------------
__global__ void deg_init_kernel(int n) {
    int i = blockIdx.x * blockDim.x + threadIdx.x;
    if (i < n) g_deg[i] = 1;  // self loop
}

__global__ void deg_count_kernel(const int* __restrict__ dst, int e) {
    int i = blockIdx.x * blockDim.x + threadIdx.x;
    if (i < e) atomicAdd(&g_deg[dst[i]], 1);
}

// ---------------------------------------------------------------------------
// Hierarchical scan of (deg-1): block-local scan + block sums. dinv fused in.
// ---------------------------------------------------------------------------
__global__ __launch_bounds__(SCAN_B)
void scan_block_kernel(int n) {
    __shared__ int s[SCAN_B];
    int tid = threadIdx.x;
    int i = blockIdx.x * SCAN_B + tid;
    int d = (i < n) ? g_deg[i] : 1;
    int c = d - 1;
    if (i < n) g_dinv[i] = rsqrtf((float)d);
    s[tid] = c;
    __syncthreads();
#pragma unroll
    for (int off = 1; off < SCAN_B; off <<= 1) {
        int v = (tid >= off) ? s[tid - off] : 0;
        __syncthreads();
        s[tid] += v;
        __syncthreads();
    }
    if (i < n) g_off[i] = s[tid] - c;   // exclusive within block
    if (tid == SCAN_B - 1) g_bsum[blockIdx.x] = s[tid];
}

__global__ __launch_bounds__(128)
void scan_bsums_kernel() {
    __shared__ int s[128];
    int tid = threadIdx.x;
    int v = (tid < NBLK) ? g_bsum[tid] : 0;
    s[tid] = v;
    __syncthreads();
#pragma unroll
    for (int off = 1; off < 128; off <<= 1) {
        int t = (tid >= off) ? s[tid - off] : 0;
        __syncthreads();
        s[tid] += t;
        __syncthreads();
    }
    if (tid < NBLK) g_bsum[tid] = s[tid] - v;  // exclusive
}

__global__ __launch_bounds__(SCAN_B)
void scan_apply_kernel(int n) {
    int i = blockIdx.x * SCAN_B + threadIdx.x;
    if (i < n) {
        int o = g_off[i] + g_bsum[blockIdx.x];
        g_off[i] = o;
        g_cur[i] = o;
    }
}

// ---------------------------------------------------------------------------
// CSR fill: bucket edges by destination (src index only — norm folded out)
// ---------------------------------------------------------------------------
__global__ __launch_bounds__(256)
void csr_fill_kernel(const int* __restrict__ src, const int* __restrict__ dst,
                     int e) {
    int i = blockIdx.x * blockDim.x + threadIdx.x;
    if (i >= e) return;
    int p = atomicAdd(&g_cur[dst[i]], 1);
    g_csr[p] = src[i];
}

// ---------------------------------------------------------------------------
// GEMM: h = x @ W  (fp32, 256x64 tile per block, 8x8 per thread)
// ---------------------------------------------------------------------------
__global__ __launch_bounds__(256, 2)
void gemm_kernel(const float* __restrict__ x, const float* __restrict__ W,
                 int n) {
    __shared__ float xs[256][33];     // +1 pad vs bank conflicts
    __shared__ float ws[32][OUT_CH];  // k-chunk x all 64 cols

    const int tx  = threadIdx.x;      // 0..7  -> 8 cols each
    const int ty  = threadIdx.y;      // 0..31 -> 8 rows each
    const int tid = ty * 8 + tx;
    const int row0 = blockIdx.x * 256;

    float acc[8][8];
#pragma unroll
    for (int i = 0; i < 8; i++)
#pragma unroll
        for (int j = 0; j < 8; j++) acc[i][j] = 0.0f;

    for (int kc = 0; kc < IN_CH; kc += 32) {
        // Load x tile: 256 rows x 32 k = 2048 float4, 8 per thread
#pragma unroll
        for (int t = 0; t < 8; t++) {
            int li = tid + t * 256;     // 0..2047
            int r  = li >> 3;           // 0..255
            int k4 = li & 7;
            float4 v = make_float4(0.f, 0.f, 0.f, 0.f);
            if (row0 + r < n)
                v = *(const float4*)(x + (size_t)(row0 + r) * IN_CH + kc + k4 * 4);
            xs[r][k4 * 4 + 0] = v.x;
            xs[r][k4 * 4 + 1] = v.y;
            xs[r][k4 * 4 + 2] = v.z;
            xs[r][k4 * 4 + 3] = v.w;
        }
        // Load W tile: 32 k x 64 cols = 512 float4, 2 per thread
#pragma unroll
        for (int t = 0; t < 2; t++) {
            int li = tid + t * 256;
            int k  = li >> 4;
            int c4 = li & 15;
            *(float4*)&ws[k][c4 * 4] =
                *(const float4*)(W + (size_t)(kc + k) * OUT_CH + c4 * 4);
        }
        __syncthreads();

#pragma unroll
        for (int kk = 0; kk < 32; kk++) {
            float4 b0 = *(float4*)&ws[kk][tx * 8];
            float4 b1 = *(float4*)&ws[kk][tx * 8 + 4];
#pragma unroll
            for (int i = 0; i < 8; i++) {
                float a = xs[ty * 8 + i][kk];
                acc[i][0] += a * b0.x; acc[i][1] += a * b0.y;
                acc[i][2] += a * b0.z; acc[i][3] += a * b0.w;
                acc[i][4] += a * b1.x; acc[i][5] += a * b1.y;
                acc[i][6] += a * b1.z; acc[i][7] += a * b1.w;
            }
        }
        __syncthreads();
    }

#pragma unroll
    for (int i = 0; i < 8; i++) {
        int r = row0 + ty * 8 + i;
        if (r < n) {
            float* hp = g_h + (size_t)r * OUT_CH + tx * 8;
            *(float4*)(hp)     = make_float4(acc[i][0], acc[i][1], acc[i][2], acc[i][3]);
            *(float4*)(hp + 4) = make_float4(acc[i][4], acc[i][5], acc[i][6], acc[i][7]);
        }
    }
}

// ---------------------------------------------------------------------------
// Aggregate: 16 threads per node (one float4 column each).
// out[v] = relu( dv * ( dv*h[v] + sum_e dinv[src]*h[src] ) + b )
// ---------------------------------------------------------------------------
__global__ __launch_bounds__(256)
void aggregate_kernel(const float* __restrict__ b, float* __restrict__ out,
                      int n) {
    int idx = blockIdx.x * blockDim.x + threadIdx.x;
    int v = idx >> 4;
    if (v >= n) return;
    int q = idx & 15;

    float dv = g_dinv[v];

    // self-loop contribution: dv * h[v]
    float4 acc = *((const float4*)(g_h + (size_t)v * OUT_CH) + q);
    acc.x *= dv; acc.y *= dv; acc.z *= dv; acc.w *= dv;

    int j = g_off[v];
    const int e = j + (g_deg[v] - 1);

    // 4-way unroll for MLP on the random h gathers
    for (; j + 3 < e; j += 4) {
        int s0 = g_csr[j + 0];
        int s1 = g_csr[j + 1];
        int s2 = g_csr[j + 2];
        int s3 = g_csr[j + 3];
        float n0 = g_dinv[s0], n1 = g_dinv[s1];
        float n2 = g_dinv[s2], n3 = g_dinv[s3];
        float4 h0 = *((const float4*)(g_h + (size_t)s0 * OUT_CH) + q);
        float4 h1 = *((const float4*)(g_h + (size_t)s1 * OUT_CH) + q);
        float4 h2 = *((const float4*)(g_h + (size_t)s2 * OUT_CH) + q);
        float4 h3 = *((const float4*)(g_h + (size_t)s3 * OUT_CH) + q);
        acc.x += n0 * h0.x + n1 * h1.x + n2 * h2.x + n3 * h3.x;
        acc.y += n0 * h0.y + n1 * h1.y + n2 * h2.y + n3 * h3.y;
        acc.z += n0 * h0.z + n1 * h1.z + n2 * h2.z + n3 * h3.z;
        acc.w += n0 * h0.w + n1 * h1.w + n2 * h2.w + n3 * h3.w;
    }
    for (; j < e; j++) {
        int s = g_csr[j];
        float nm = g_dinv[s];
        float4 hv = *((const float4*)(g_h + (size_t)s * OUT_CH) + q);
        acc.x += nm * hv.x; acc.y += nm * hv.y;
        acc.z += nm * hv.z; acc.w += nm * hv.w;
    }

    float4 bb = ((const float4*)b)[q];
    acc.x = fmaxf(fmaf(dv, acc.x, bb.x), 0.f);
    acc.y = fmaxf(fmaf(dv, acc.y, bb.y), 0.f);
    acc.z = fmaxf(fmaf(dv, acc.z, bb.z), 0.f);
    acc.w = fmaxf(fmaf(dv, acc.w, bb.w), 0.f);
    *((float4*)(out + (size_t)v * OUT_CH) + q) = acc;
}

// ---------------------------------------------------------------------------
extern "C" void kernel_launch(void* const* d_in, const int* in_sizes, int n_in,
                              void* d_out, int out_size) {
    const float* x  = (const float*)d_in[0];
    const int*   ei = (const int*)d_in[1];
    const float* W  = (const float*)d_in[2];
    const float* b  = (const float*)d_in[3];
    float*       out = (float*)d_out;

    const int n = in_sizes[0] / IN_CH;   // 100000
    const int e = in_sizes[1] / 2;       // 1600000
    const int* src = ei;                 // edge_index[0]
    const int* dst = ei + e;             // edge_index[1]

    // Lazy one-time creation (first call is the non-captured correctness run)
    static cudaStream_t s2 = nullptr;
    static cudaEvent_t ev_fork = nullptr, ev_join = nullptr;
    if (s2 == nullptr) {
        cudaStreamCreateWithFlags(&s2, cudaStreamNonBlocking);
        cudaEventCreateWithFlags(&ev_fork, cudaEventDisableTiming);
        cudaEventCreateWithFlags(&ev_join, cudaEventDisableTiming);
    }

    // Fork: GEMM on s2 runs concurrently with the degree/CSR chain
    cudaEventRecord(ev_fork, 0);
    cudaStreamWaitEvent(s2, ev_fork, 0);

    dim3 tb(8, 32);
    gemm_kernel<<<(n + 255) / 256, tb, 0, s2>>>(x, W, n);

    deg_init_kernel<<<(n + 255) / 256, 256>>>(n);
    deg_count_kernel<<<(e + 255) / 256, 256>>>(dst, e);

    int nblk = (n + SCAN_B - 1) / SCAN_B;
    scan_block_kernel<<<nblk, SCAN_B>>>(n);
    scan_bsums_kernel<<<1, 128>>>();
    scan_apply_kernel<<<nblk, SCAN_B>>>(n);

    csr_fill_kernel<<<(e + 255) / 256, 256>>>(src, dst, e);

    // Join: aggregate needs both h (s2) and the CSR (stream 0)
    cudaEventRecord(ev_join, s2);
    cudaStreamWaitEvent(0, ev_join, 0);

    long ag_threads = (long)n * 16;
    aggregate_kernel<<<(int)((ag_threads + 255) / 256), 256>>>(b, out, n);
}

// round 8
// speedup vs baseline: 1.2480x; 1.1000x over previous
#include <cuda_runtime.h>
#include <cuda_fp16.h>
#include <stdint.h>

#define IN_CH   128
#define OUT_CH  64
#define N_MAX   100000
#define E_MAX   1600000
#define SCAN_B  1024
#define NBLK    ((N_MAX + SCAN_B - 1) / SCAN_B)   // 98

// Scratch (device globals — no runtime allocation allowed)
__device__ __half2 g_hh[(size_t)N_MAX * (OUT_CH / 2)];  // 12.8 MB: h in fp16
__device__ float g_dinv[N_MAX];
__device__ int   g_deg[N_MAX];                  // in-edge count (EXCL self loop)
__device__ int   g_off[N_MAX];                  // CSR offsets
__device__ int   g_cur[N_MAX];                  // fill cursors
__device__ int   g_bsum[NBLK];                  // per-block sums for scan
__device__ int   g_csr[E_MAX];                  // src node per edge (dst-bucketed)

// ---------------------------------------------------------------------------
// Degree count (vectorized int4 reads; deg starts at 0 via memsetAsync)
// ---------------------------------------------------------------------------
__global__ void deg_count_kernel(const int* __restrict__ dst, int e) {
    int i = blockIdx.x * blockDim.x + threadIdx.x;
    int base = i * 4;
    if (base + 3 < e) {
        int4 d = *(const int4*)(dst + base);
        atomicAdd(&g_deg[d.x], 1);
        atomicAdd(&g_deg[d.y], 1);
        atomicAdd(&g_deg[d.z], 1);
        atomicAdd(&g_deg[d.w], 1);
    } else {
        for (int k = base; k < e; k++) atomicAdd(&g_deg[dst[k]], 1);
    }
}

// ---------------------------------------------------------------------------
// Hierarchical scan of deg: block-local scan + block sums. dinv fused in.
// ---------------------------------------------------------------------------
__global__ __launch_bounds__(SCAN_B)
void scan_block_kernel(int n) {
    __shared__ int s[SCAN_B];
    int tid = threadIdx.x;
    int i = blockIdx.x * SCAN_B + tid;
    int c = (i < n) ? g_deg[i] : 0;
    if (i < n) g_dinv[i] = rsqrtf((float)(c + 1));
    s[tid] = c;
    __syncthreads();
#pragma unroll
    for (int off = 1; off < SCAN_B; off <<= 1) {
        int v = (tid >= off) ? s[tid - off] : 0;
        __syncthreads();
        s[tid] += v;
        __syncthreads();
    }
    if (i < n) g_off[i] = s[tid] - c;   // exclusive within block
    if (tid == SCAN_B - 1) g_bsum[blockIdx.x] = s[tid];
}

__global__ __launch_bounds__(128)
void scan_bsums_kernel() {
    __shared__ int s[128];
    int tid = threadIdx.x;
    int v = (tid < NBLK) ? g_bsum[tid] : 0;
    s[tid] = v;
    __syncthreads();
#pragma unroll
    for (int off = 1; off < 128; off <<= 1) {
        int t = (tid >= off) ? s[tid - off] : 0;
        __syncthreads();
        s[tid] += t;
        __syncthreads();
    }
    if (tid < NBLK) g_bsum[tid] = s[tid] - v;  // exclusive
}

__global__ __launch_bounds__(SCAN_B)
void scan_apply_kernel(int n) {
    int i = blockIdx.x * SCAN_B + threadIdx.x;
    if (i < n) {
        int o = g_off[i] + g_bsum[blockIdx.x];
        g_off[i] = o;
        g_cur[i] = o;
    }
}

// ---------------------------------------------------------------------------
// CSR fill: bucket edges by destination (vectorized int4 reads)
// ---------------------------------------------------------------------------
__global__ __launch_bounds__(256)
void csr_fill_kernel(const int* __restrict__ src, const int* __restrict__ dst,
                     int e) {
    int i = blockIdx.x * blockDim.x + threadIdx.x;
    int base = i * 4;
    if (base + 3 < e) {
        int4 d = *(const int4*)(dst + base);
        int4 s = *(const int4*)(src + base);
        g_csr[atomicAdd(&g_cur[d.x], 1)] = s.x;
        g_csr[atomicAdd(&g_cur[d.y], 1)] = s.y;
        g_csr[atomicAdd(&g_cur[d.z], 1)] = s.z;
        g_csr[atomicAdd(&g_cur[d.w], 1)] = s.w;
    } else {
        for (int k = base; k < e; k++)
            g_csr[atomicAdd(&g_cur[dst[k]], 1)] = src[k];
    }
}

// ---------------------------------------------------------------------------
// GEMM: h = x @ W  (fp32 math, 256x64 tile, 8x8 per thread, fp16 output)
// ---------------------------------------------------------------------------
__global__ __launch_bounds__(256, 2)
void gemm_kernel(const float* __restrict__ x, const float* __restrict__ W,
                 int n) {
    __shared__ float xs[256][33];     // +1 pad vs bank conflicts
    __shared__ float ws[32][OUT_CH];  // k-chunk x all 64 cols

    const int tx  = threadIdx.x;      // 0..7  -> 8 cols each
    const int ty  = threadIdx.y;      // 0..31 -> 8 rows each
    const int tid = ty * 8 + tx;
    const int row0 = blockIdx.x * 256;

    float acc[8][8];
#pragma unroll
    for (int i = 0; i < 8; i++)
#pragma unroll
        for (int j = 0; j < 8; j++) acc[i][j] = 0.0f;

    for (int kc = 0; kc < IN_CH; kc += 32) {
#pragma unroll
        for (int t = 0; t < 8; t++) {
            int li = tid + t * 256;     // 0..2047
            int r  = li >> 3;           // 0..255
            int k4 = li & 7;
            float4 v = make_float4(0.f, 0.f, 0.f, 0.f);
            if (row0 + r < n)
                v = *(const float4*)(x + (size_t)(row0 + r) * IN_CH + kc + k4 * 4);
            xs[r][k4 * 4 + 0] = v.x;
            xs[r][k4 * 4 + 1] = v.y;
            xs[r][k4 * 4 + 2] = v.z;
            xs[r][k4 * 4 + 3] = v.w;
        }
#pragma unroll
        for (int t = 0; t < 2; t++) {
            int li = tid + t * 256;
            int k  = li >> 4;
            int c4 = li & 15;
            *(float4*)&ws[k][c4 * 4] =
                *(const float4*)(W + (size_t)(kc + k) * OUT_CH + c4 * 4);
        }
        __syncthreads();

#pragma unroll
        for (int kk = 0; kk < 32; kk++) {
            float4 b0 = *(float4*)&ws[kk][tx * 8];
            float4 b1 = *(float4*)&ws[kk][tx * 8 + 4];
#pragma unroll
            for (int i = 0; i < 8; i++) {
                float a = xs[ty * 8 + i][kk];
                acc[i][0] += a * b0.x; acc[i][1] += a * b0.y;
                acc[i][2] += a * b0.z; acc[i][3] += a * b0.w;
                acc[i][4] += a * b1.x; acc[i][5] += a * b1.y;
                acc[i][6] += a * b1.z; acc[i][7] += a * b1.w;
            }
        }
        __syncthreads();
    }

    // Epilogue: convert to fp16 and store as one 16B transaction per row-chunk
#pragma unroll
    for (int i = 0; i < 8; i++) {
        int r = row0 + ty * 8 + i;
        if (r < n) {
            __half2 hbuf[4];
            hbuf[0] = __floats2half2_rn(acc[i][0], acc[i][1]);
            hbuf[1] = __floats2half2_rn(acc[i][2], acc[i][3]);
            hbuf[2] = __floats2half2_rn(acc[i][4], acc[i][5]);
            hbuf[3] = __floats2half2_rn(acc[i][6], acc[i][7]);
            __half2* hp = g_hh + (size_t)r * (OUT_CH / 2) + tx * 4;
            *(uint4*)hp = *(const uint4*)hbuf;
        }
    }
}

// ---------------------------------------------------------------------------
// Aggregate: 16 threads per node, each owns 4 channels (2 half2 = 8B/edge).
// out[v] = relu( dv * ( dv*h[v] + sum_e dinv[src]*h[src] ) + b )
// ---------------------------------------------------------------------------
__device__ __forceinline__ float4 h2pair_to_f4(uint2 u) {
    __half2 a = *(__half2*)&u.x;
    __half2 b = *(__half2*)&u.y;
    float2 fa = __half22float2(a);
    float2 fb = __half22float2(b);
    return make_float4(fa.x, fa.y, fb.x, fb.y);
}

__global__ __launch_bounds__(256)
void aggregate_kernel(const float* __restrict__ b, float* __restrict__ out,
                      int n) {
    int idx = blockIdx.x * blockDim.x + threadIdx.x;
    int v = idx >> 4;
    if (v >= n) return;
    int q = idx & 15;

    const uint2* hh = (const uint2*)g_hh;   // 8B granules; node stride 16

    float dv = g_dinv[v];

    // self-loop contribution: dv * h[v]
    float4 acc = h2pair_to_f4(hh[(size_t)v * 16 + q]);
    acc.x *= dv; acc.y *= dv; acc.z *= dv; acc.w *= dv;

    int j = g_off[v];
    const int e = j + g_deg[v];

    // 8-way unroll for MLP on the random h gathers
    for (; j + 7 < e; j += 8) {
        int   si[8];
        float nd[8];
        uint2 hv[8];
#pragma unroll
        for (int t = 0; t < 8; t++) si[t] = g_csr[j + t];
#pragma unroll
        for (int t = 0; t < 8; t++) nd[t] = g_dinv[si[t]];
#pragma unroll
        for (int t = 0; t < 8; t++) hv[t] = hh[(size_t)si[t] * 16 + q];
#pragma unroll
        for (int t = 0; t < 8; t++) {
            float4 f = h2pair_to_f4(hv[t]);
            acc.x = fmaf(nd[t], f.x, acc.x);
            acc.y = fmaf(nd[t], f.y, acc.y);
            acc.z = fmaf(nd[t], f.z, acc.z);
            acc.w = fmaf(nd[t], f.w, acc.w);
        }
    }
    for (; j < e; j++) {
        int s = g_csr[j];
        float nm = g_dinv[s];
        float4 f = h2pair_to_f4(hh[(size_t)s * 16 + q]);
        acc.x = fmaf(nm, f.x, acc.x);
        acc.y = fmaf(nm, f.y, acc.y);
        acc.z = fmaf(nm, f.z, acc.z);
        acc.w = fmaf(nm, f.w, acc.w);
    }

    float4 bb = ((const float4*)b)[q];
    acc.x = fmaxf(fmaf(dv, acc.x, bb.x), 0.f);
    acc.y = fmaxf(fmaf(dv, acc.y, bb.y), 0.f);
    acc.z = fmaxf(fmaf(dv, acc.z, bb.z), 0.f);
    acc.w = fmaxf(fmaf(dv, acc.w, bb.w), 0.f);
    *((float4*)(out + (size_t)v * OUT_CH) + q) = acc;
}

// ---------------------------------------------------------------------------
extern "C" void kernel_launch(void* const* d_in, const int* in_sizes, int n_in,
                              void* d_out, int out_size) {
    const float* x  = (const float*)d_in[0];
    const int*   ei = (const int*)d_in[1];
    const float* W  = (const float*)d_in[2];
    const float* b  = (const float*)d_in[3];
    float*       out = (float*)d_out;

    const int n = in_sizes[0] / IN_CH;   // 100000
    const int e = in_sizes[1] / 2;       // 1600000
    const int* src = ei;                 // edge_index[0]
    const int* dst = ei + e;             // edge_index[1]

    // Lazy one-time setup (first call is the non-captured correctness run)
    static cudaStream_t s2 = nullptr;
    static cudaEvent_t ev_fork = nullptr, ev_join = nullptr;
    static void* deg_ptr = nullptr;
    if (s2 == nullptr) {
        cudaStreamCreateWithFlags(&s2, cudaStreamNonBlocking);
        cudaEventCreateWithFlags(&ev_fork, cudaEventDisableTiming);
        cudaEventCreateWithFlags(&ev_join, cudaEventDisableTiming);
        cudaGetSymbolAddress(&deg_ptr, g_deg);
    }

    // Fork: GEMM on s2 runs concurrently with the degree/CSR chain
    cudaEventRecord(ev_fork, 0);
    cudaStreamWaitEvent(s2, ev_fork, 0);

    dim3 tb(8, 32);
    gemm_kernel<<<(n + 255) / 256, tb, 0, s2>>>(x, W, n);

    cudaMemsetAsync(deg_ptr, 0, (size_t)n * sizeof(int), 0);
    deg_count_kernel<<<(e / 4 + 255) / 256, 256>>>(dst, e);

    int nblk = (n + SCAN_B - 1) / SCAN_B;
    scan_block_kernel<<<nblk, SCAN_B>>>(n);
    scan_bsums_kernel<<<1, 128>>>();
    scan_apply_kernel<<<nblk, SCAN_B>>>(n);

    csr_fill_kernel<<<(e / 4 + 255) / 256, 256>>>(src, dst, e);

    // Join: aggregate needs both h (s2) and the CSR (stream 0)
    cudaEventRecord(ev_join, s2);
    cudaStreamWaitEvent(0, ev_join, 0);

    long ag_threads = (long)n * 16;
    aggregate_kernel<<<(int)((ag_threads + 255) / 256), 256>>>(b, out, n);
}

// round 9
// speedup vs baseline: 1.2720x; 1.0192x over previous
#include <cuda_runtime.h>
#include <cuda_fp16.h>
#include <stdint.h>

#define IN_CH   128
#define OUT_CH  64
#define N_MAX   100000
#define E_MAX   1600000
#define SCAN_B  1024
#define NBLK    ((N_MAX + SCAN_B - 1) / SCAN_B)   // 98

// Scratch (device globals — no runtime allocation allowed)
__device__ __half2 g_hh[(size_t)N_MAX * (OUT_CH / 2)];  // 12.8 MB: h in fp16
__device__ float g_dinv[N_MAX];
__device__ int   g_deg[N_MAX];                  // in-edge count (EXCL self loop)
__device__ int   g_off[N_MAX];                  // CSR offsets
__device__ int   g_cur[N_MAX];                  // fill cursors; == end after fill
__device__ int   g_bsum[NBLK];                  // per-block raw sums for scan
__device__ int   g_csr[E_MAX];                  // src node per edge (dst-bucketed)

// ---------------------------------------------------------------------------
// Degree count (vectorized int4 reads; deg starts at 0 via memsetAsync)
// ---------------------------------------------------------------------------
__global__ void deg_count_kernel(const int* __restrict__ dst, int e) {
    int i = blockIdx.x * blockDim.x + threadIdx.x;
    int base = i * 4;
    if (base + 3 < e) {
        int4 d = *(const int4*)(dst + base);
        atomicAdd(&g_deg[d.x], 1);
        atomicAdd(&g_deg[d.y], 1);
        atomicAdd(&g_deg[d.z], 1);
        atomicAdd(&g_deg[d.w], 1);
    } else {
        for (int k = base; k < e; k++) atomicAdd(&g_deg[dst[k]], 1);
    }
}

// ---------------------------------------------------------------------------
// Scan stage 1: block-local exclusive scan of deg; raw block sums out.
// dinv fused in.
// ---------------------------------------------------------------------------
__global__ __launch_bounds__(SCAN_B)
void scan_block_kernel(int n) {
    __shared__ int s[SCAN_B];
    int tid = threadIdx.x;
    int i = blockIdx.x * SCAN_B + tid;
    int c = (i < n) ? g_deg[i] : 0;
    if (i < n) g_dinv[i] = rsqrtf((float)(c + 1));
    s[tid] = c;
    __syncthreads();
#pragma unroll
    for (int off = 1; off < SCAN_B; off <<= 1) {
        int v = (tid >= off) ? s[tid - off] : 0;
        __syncthreads();
        s[tid] += v;
        __syncthreads();
    }
    if (i < n) g_off[i] = s[tid] - c;   // exclusive within block
    if (tid == SCAN_B - 1) g_bsum[blockIdx.x] = s[tid];
}

// ---------------------------------------------------------------------------
// Scan stage 2: each block inlines the prefix over raw block sums, applies it.
// ---------------------------------------------------------------------------
__global__ __launch_bounds__(SCAN_B)
void scan_apply_kernel(int n) {
    __shared__ int sb[128];
    int tid = threadIdx.x;
    int b = blockIdx.x;
    if (tid < 128) sb[tid] = (tid < b) ? g_bsum[tid] : 0;  // b < NBLK <= 98 < 128
    __syncthreads();
#pragma unroll
    for (int off = 64; off > 0; off >>= 1) {
        if (tid < off) sb[tid] += sb[tid + off];
        __syncthreads();
    }
    int base = sb[0];
    int i = b * SCAN_B + tid;
    if (i < n) {
        int o = g_off[i] + base;
        g_off[i] = o;
        g_cur[i] = o;
    }
}

// ---------------------------------------------------------------------------
// CSR fill: bucket edges by destination (vectorized int4 reads).
// After this kernel g_cur[v] == g_off[v] + deg[v] (the bucket end).
// ---------------------------------------------------------------------------
__global__ __launch_bounds__(256)
void csr_fill_kernel(const int* __restrict__ src, const int* __restrict__ dst,
                     int e) {
    int i = blockIdx.x * blockDim.x + threadIdx.x;
    int base = i * 4;
    if (base + 3 < e) {
        int4 d = *(const int4*)(dst + base);
        int4 s = *(const int4*)(src + base);
        g_csr[atomicAdd(&g_cur[d.x], 1)] = s.x;
        g_csr[atomicAdd(&g_cur[d.y], 1)] = s.y;
        g_csr[atomicAdd(&g_cur[d.z], 1)] = s.z;
        g_csr[atomicAdd(&g_cur[d.w], 1)] = s.w;
    } else {
        for (int k = base; k < e; k++)
            g_csr[atomicAdd(&g_cur[dst[k]], 1)] = src[k];
    }
}

// ---------------------------------------------------------------------------
// GEMM: h = x @ W  (fp32 math, 256x64 tile, 8x8 per thread, fp16 output)
// ---------------------------------------------------------------------------
__global__ __launch_bounds__(256, 2)
void gemm_kernel(const float* __restrict__ x, const float* __restrict__ W,
                 int n) {
    __shared__ float xs[256][33];     // +1 pad vs bank conflicts
    __shared__ float ws[32][OUT_CH];  // k-chunk x all 64 cols

    const int tx  = threadIdx.x;      // 0..7  -> 8 cols each
    const int ty  = threadIdx.y;      // 0..31 -> 8 rows each
    const int tid = ty * 8 + tx;
    const int row0 = blockIdx.x * 256;

    float acc[8][8];
#pragma unroll
    for (int i = 0; i < 8; i++)
#pragma unroll
        for (int j = 0; j < 8; j++) acc[i][j] = 0.0f;

    for (int kc = 0; kc < IN_CH; kc += 32) {
#pragma unroll
        for (int t = 0; t < 8; t++) {
            int li = tid + t * 256;     // 0..2047
            int r  = li >> 3;           // 0..255
            int k4 = li & 7;
            float4 v = make_float4(0.f, 0.f, 0.f, 0.f);
            if (row0 + r < n)
                v = *(const float4*)(x + (size_t)(row0 + r) * IN_CH + kc + k4 * 4);
            xs[r][k4 * 4 + 0] = v.x;
            xs[r][k4 * 4 + 1] = v.y;
            xs[r][k4 * 4 + 2] = v.z;
            xs[r][k4 * 4 + 3] = v.w;
        }
#pragma unroll
        for (int t = 0; t < 2; t++) {
            int li = tid + t * 256;
            int k  = li >> 4;
            int c4 = li & 15;
            *(float4*)&ws[k][c4 * 4] =
                *(const float4*)(W + (size_t)(kc + k) * OUT_CH + c4 * 4);
        }
        __syncthreads();

#pragma unroll
        for (int kk = 0; kk < 32; kk++) {
            float4 b0 = *(float4*)&ws[kk][tx * 8];
            float4 b1 = *(float4*)&ws[kk][tx * 8 + 4];
#pragma unroll
            for (int i = 0; i < 8; i++) {
                float a = xs[ty * 8 + i][kk];
                acc[i][0] += a * b0.x; acc[i][1] += a * b0.y;
                acc[i][2] += a * b0.z; acc[i][3] += a * b0.w;
                acc[i][4] += a * b1.x; acc[i][5] += a * b1.y;
                acc[i][6] += a * b1.z; acc[i][7] += a * b1.w;
            }
        }
        __syncthreads();
    }

    // Epilogue: convert to fp16 and store as one 16B transaction per row-chunk
#pragma unroll
    for (int i = 0; i < 8; i++) {
        int r = row0 + ty * 8 + i;
        if (r < n) {
            __half2 hbuf[4];
            hbuf[0] = __floats2half2_rn(acc[i][0], acc[i][1]);
            hbuf[1] = __floats2half2_rn(acc[i][2], acc[i][3]);
            hbuf[2] = __floats2half2_rn(acc[i][4], acc[i][5]);
            hbuf[3] = __floats2half2_rn(acc[i][6], acc[i][7]);
            __half2* hp = g_hh + (size_t)r * (OUT_CH / 2) + tx * 4;
            *(uint4*)hp = *(const uint4*)hbuf;
        }
    }
}

// ---------------------------------------------------------------------------
// Aggregate: 8 threads per node, each owns 8 channels (one uint4 = 16B/edge).
// Warp covers 4 nodes -> one h-load instruction serves 4 edges (512B).
// out[v] = relu( dv * ( dv*h[v] + sum_e dinv[src]*h[src] ) + b )
// ---------------------------------------------------------------------------
__device__ __forceinline__ void h8_to_f8(uint4 u, float* f) {
    const __half2* hp = (const __half2*)&u;
    float2 f0 = __half22float2(hp[0]);
    float2 f1 = __half22float2(hp[1]);
    float2 f2 = __half22float2(hp[2]);
    float2 f3 = __half22float2(hp[3]);
    f[0] = f0.x; f[1] = f0.y; f[2] = f1.x; f[3] = f1.y;
    f[4] = f2.x; f[5] = f2.y; f[6] = f3.x; f[7] = f3.y;
}

__global__ __launch_bounds__(256)
void aggregate_kernel(const float* __restrict__ b, float* __restrict__ out,
                      int n) {
    int idx = blockIdx.x * blockDim.x + threadIdx.x;
    int v = idx >> 3;
    if (v >= n) return;
    int q = idx & 7;

    const uint4* hh4 = (const uint4*)g_hh;   // 16B granules; node stride 8

    float dv = g_dinv[v];

    // self-loop contribution: dv * h[v]
    float a[8];
    {
        float f[8];
        h8_to_f8(hh4[(size_t)v * 8 + q], f);
#pragma unroll
        for (int k = 0; k < 8; k++) a[k] = dv * f[k];
    }

    int j = g_off[v];
    const int end = g_cur[v];    // == off + deg after csr_fill

    for (; j < end; j += 8) {
        int   s[8];
        float nm[8];
        uint4 hv[8];
#pragma unroll
        for (int t = 0; t < 8; t++)
            s[t] = (j + t < end) ? g_csr[j + t] : 0;
#pragma unroll
        for (int t = 0; t < 8; t++)
            nm[t] = (j + t < end) ? g_dinv[s[t]] : 0.f;
#pragma unroll
        for (int t = 0; t < 8; t++)
            hv[t] = hh4[(size_t)s[t] * 8 + q];
#pragma unroll
        for (int t = 0; t < 8; t++) {
            float f[8];
            h8_to_f8(hv[t], f);
#pragma unroll
            for (int k = 0; k < 8; k++) a[k] = fmaf(nm[t], f[k], a[k]);
        }
    }

    // bias + relu; thread q covers channels [q*8, q*8+8)
    const float4* bb = (const float4*)b;
    float4 b0 = bb[q * 2], b1 = bb[q * 2 + 1];
    float4 o0, o1;
    o0.x = fmaxf(fmaf(dv, a[0], b0.x), 0.f);
    o0.y = fmaxf(fmaf(dv, a[1], b0.y), 0.f);
    o0.z = fmaxf(fmaf(dv, a[2], b0.z), 0.f);
    o0.w = fmaxf(fmaf(dv, a[3], b0.w), 0.f);
    o1.x = fmaxf(fmaf(dv, a[4], b1.x), 0.f);
    o1.y = fmaxf(fmaf(dv, a[5], b1.y), 0.f);
    o1.z = fmaxf(fmaf(dv, a[6], b1.z), 0.f);
    o1.w = fmaxf(fmaf(dv, a[7], b1.w), 0.f);
    float4* op = (float4*)(out + (size_t)v * OUT_CH);
    op[q * 2]     = o0;
    op[q * 2 + 1] = o1;
}

// ---------------------------------------------------------------------------
extern "C" void kernel_launch(void* const* d_in, const int* in_sizes, int n_in,
                              void* d_out, int out_size) {
    const float* x  = (const float*)d_in[0];
    const int*   ei = (const int*)d_in[1];
    const float* W  = (const float*)d_in[2];
    const float* b  = (const float*)d_in[3];
    float*       out = (float*)d_out;

    const int n = in_sizes[0] / IN_CH;   // 100000
    const int e = in_sizes[1] / 2;       // 1600000
    const int* src = ei;                 // edge_index[0]
    const int* dst = ei + e;             // edge_index[1]

    // Lazy one-time setup (first call is the non-captured correctness run)
    static cudaStream_t s2 = nullptr;
    static cudaEvent_t ev_fork = nullptr, ev_join = nullptr;
    static void* deg_ptr = nullptr;
    if (s2 == nullptr) {
        cudaStreamCreateWithFlags(&s2, cudaStreamNonBlocking);
        cudaEventCreateWithFlags(&ev_fork, cudaEventDisableTiming);
        cudaEventCreateWithFlags(&ev_join, cudaEventDisableTiming);
        cudaGetSymbolAddress(&deg_ptr, g_deg);
    }

    // Fork: GEMM on s2 runs concurrently with the degree/CSR chain
    cudaEventRecord(ev_fork, 0);
    cudaStreamWaitEvent(s2, ev_fork, 0);

    dim3 tb(8, 32);
    gemm_kernel<<<(n + 255) / 256, tb, 0, s2>>>(x, W, n);

    cudaMemsetAsync(deg_ptr, 0, (size_t)n * sizeof(int), 0);
    deg_count_kernel<<<(e / 4 + 255) / 256, 256>>>(dst, e);

    int nblk = (n + SCAN_B - 1) / SCAN_B;
    scan_block_kernel<<<nblk, SCAN_B>>>(n);
    scan_apply_kernel<<<nblk, SCAN_B>>>(n);

    csr_fill_kernel<<<(e / 4 + 255) / 256, 256>>>(src, dst, e);

    // Join: aggregate needs both h (s2) and the CSR (stream 0)
    cudaEventRecord(ev_join, s2);
    cudaStreamWaitEvent(0, ev_join, 0);

    long ag_threads = (long)n * 8;
    aggregate_kernel<<<(int)((ag_threads + 255) / 256), 256>>>(b, out, n);
}